// round 2
// baseline (speedup 1.0000x reference)
#include <cuda_runtime.h>
#include <cuda_bf16.h>

// Problem: N = 50000 nodes, F = 2048 features, OUT = 256 outputs
//   v[i]   = sum_n adj[n] * fm[n, i]           (column-weighted sum, 409.6 MB read)
//   out[j] = sum_i (A[i] * v[i]) * B[i, j]     (tiny GEMV, ~2 MB)
// HBM-bound; target ~60 us on B200-class HBM.

#define F_DIM 2048
#define OUT_DIM 256
#define P1_THREADS 512            // thread t owns columns [4t, 4t+4) as float4
#define P1_BLOCKS 592             // 4 CTAs/SM * 148 SMs
#define ADJ_TILE 256              // rows of adj staged in shared per iteration
#define P2_BLOCKS 64
#define P2_ROWS_PER_BLOCK (F_DIM / P2_BLOCKS)   // 32

__device__ float g_v[F_DIM];

// ---------------------------------------------------------------------------
// Phase 0: zero scratch + output (harness poisons d_out to 0xAA; phase 2 uses
// atomic accumulation so out must start at zero).
// ---------------------------------------------------------------------------
__global__ void zero_kernel(float* __restrict__ out) {
    int i = blockIdx.x * blockDim.x + threadIdx.x;   // 0..2047 with 8x256
    g_v[i] = 0.0f;
    if (i < OUT_DIM) out[i] = 0.0f;
}

// ---------------------------------------------------------------------------
// Phase 1: v[i] = sum_n adj[n] * fm[n, i]
// Block owns a contiguous chunk of ~85 rows. Per row the block reads the full
// 8 KB row perfectly coalesced (512 threads x float4). adj is staged through
// shared in ADJ_TILE chunks. Row loop unrolled by 8 for MLP.
// ---------------------------------------------------------------------------
__global__ __launch_bounds__(P1_THREADS, 4)
void colsum_kernel(const float* __restrict__ adj,
                   const float* __restrict__ fm,
                   int n_rows, int rows_per_block) {
    __shared__ float s_adj[ADJ_TILE];
    const int t = threadIdx.x;                       // 0..511
    const int r0 = blockIdx.x * rows_per_block;
    int r1 = r0 + rows_per_block;
    if (r1 > n_rows) r1 = n_rows;

    const float4* __restrict__ fm4 = (const float4*)fm;

    float ax = 0.f, ay = 0.f, az = 0.f, aw = 0.f;

    for (int tile = r0; tile < r1; tile += ADJ_TILE) {
        int tlen = r1 - tile;
        if (tlen > ADJ_TILE) tlen = ADJ_TILE;

        __syncthreads();
        if (t < tlen) s_adj[t] = __ldg(adj + tile + t);
        __syncthreads();

        int k = 0;
        for (; k + 8 <= tlen; k += 8) {
            const size_t base = (size_t)(tile + k) * (F_DIM / 4) + t;
            // 8 independent global loads in flight before any FMA consumes them.
            float4 x0 = __ldg(fm4 + base + 0 * (F_DIM / 4));
            float4 x1 = __ldg(fm4 + base + 1 * (F_DIM / 4));
            float4 x2 = __ldg(fm4 + base + 2 * (F_DIM / 4));
            float4 x3 = __ldg(fm4 + base + 3 * (F_DIM / 4));
            float4 x4 = __ldg(fm4 + base + 4 * (F_DIM / 4));
            float4 x5 = __ldg(fm4 + base + 5 * (F_DIM / 4));
            float4 x6 = __ldg(fm4 + base + 6 * (F_DIM / 4));
            float4 x7 = __ldg(fm4 + base + 7 * (F_DIM / 4));
            float a0 = s_adj[k + 0], a1 = s_adj[k + 1];
            float a2 = s_adj[k + 2], a3 = s_adj[k + 3];
            float a4 = s_adj[k + 4], a5 = s_adj[k + 5];
            float a6 = s_adj[k + 6], a7 = s_adj[k + 7];
            ax = fmaf(a0, x0.x, ax); ay = fmaf(a0, x0.y, ay);
            az = fmaf(a0, x0.z, az); aw = fmaf(a0, x0.w, aw);
            ax = fmaf(a1, x1.x, ax); ay = fmaf(a1, x1.y, ay);
            az = fmaf(a1, x1.z, az); aw = fmaf(a1, x1.w, aw);
            ax = fmaf(a2, x2.x, ax); ay = fmaf(a2, x2.y, ay);
            az = fmaf(a2, x2.z, az); aw = fmaf(a2, x2.w, aw);
            ax = fmaf(a3, x3.x, ax); ay = fmaf(a3, x3.y, ay);
            az = fmaf(a3, x3.z, az); aw = fmaf(a3, x3.w, aw);
            ax = fmaf(a4, x4.x, ax); ay = fmaf(a4, x4.y, ay);
            az = fmaf(a4, x4.z, az); aw = fmaf(a4, x4.w, aw);
            ax = fmaf(a5, x5.x, ax); ay = fmaf(a5, x5.y, ay);
            az = fmaf(a5, x5.z, az); aw = fmaf(a5, x5.w, aw);
            ax = fmaf(a6, x6.x, ax); ay = fmaf(a6, x6.y, ay);
            az = fmaf(a6, x6.z, az); aw = fmaf(a6, x6.w, aw);
            ax = fmaf(a7, x7.x, ax); ay = fmaf(a7, x7.y, ay);
            az = fmaf(a7, x7.z, az); aw = fmaf(a7, x7.w, aw);
        }
        for (; k < tlen; ++k) {
            float a = s_adj[k];
            float4 x = __ldg(fm4 + (size_t)(tile + k) * (F_DIM / 4) + t);
            ax = fmaf(a, x.x, ax); ay = fmaf(a, x.y, ay);
            az = fmaf(a, x.z, az); aw = fmaf(a, x.w, aw);
        }
    }

    atomicAdd(&g_v[4 * t + 0], ax);
    atomicAdd(&g_v[4 * t + 1], ay);
    atomicAdd(&g_v[4 * t + 2], az);
    atomicAdd(&g_v[4 * t + 3], aw);
}

// ---------------------------------------------------------------------------
// Phase 2: out[j] = sum_i A[i]*v[i]*B[i, j].
// 64 blocks split the i-dimension (32 rows each); thread j = output column.
// B rows are coalesced ([F, OUT] row-major).
// ---------------------------------------------------------------------------
__global__ __launch_bounds__(OUT_DIM)
void gemv_kernel(const float* __restrict__ A,
                 const float* __restrict__ B,
                 float* __restrict__ out) {
    __shared__ float av[P2_ROWS_PER_BLOCK];
    const int j = threadIdx.x;                       // 0..255
    const int i0 = blockIdx.x * P2_ROWS_PER_BLOCK;

    if (j < P2_ROWS_PER_BLOCK) {
        int i = i0 + j;
        av[j] = A[i] * g_v[i];
    }
    __syncthreads();

    float s0 = 0.f, s1 = 0.f, s2 = 0.f, s3 = 0.f;
#pragma unroll
    for (int k = 0; k < P2_ROWS_PER_BLOCK; k += 4) {
        size_t base = (size_t)(i0 + k) * OUT_DIM + j;
        s0 = fmaf(av[k + 0], __ldg(B + base + 0 * OUT_DIM), s0);
        s1 = fmaf(av[k + 1], __ldg(B + base + 1 * OUT_DIM), s1);
        s2 = fmaf(av[k + 2], __ldg(B + base + 2 * OUT_DIM), s2);
        s3 = fmaf(av[k + 3], __ldg(B + base + 3 * OUT_DIM), s3);
    }
    atomicAdd(&out[j], (s0 + s1) + (s2 + s3));
}

// ---------------------------------------------------------------------------
// Launch. Inputs (metadata order): node_adjacency [1,50000], feature_map
// [50000,2048], A [2048,1], B [2048,256], fe_mask_rate (scalar == 0, ignored).
// Output: float32 [1,256].
// ---------------------------------------------------------------------------
extern "C" void kernel_launch(void* const* d_in, const int* in_sizes, int n_in,
                              void* d_out, int out_size) {
    const float* adj = (const float*)d_in[0];
    const float* fm  = (const float*)d_in[1];
    const float* A   = (const float*)d_in[2];
    const float* B   = (const float*)d_in[3];
    float* out = (float*)d_out;

    const int n_rows = in_sizes[0];                  // 50000
    const int rows_per_block = (n_rows + P1_BLOCKS - 1) / P1_BLOCKS;

    zero_kernel<<<F_DIM / 256, 256>>>(out);
    colsum_kernel<<<P1_BLOCKS, P1_THREADS>>>(adj, fm, n_rows, rows_per_block);
    gemv_kernel<<<P2_BLOCKS, OUT_DIM>>>(A, B, out);
}

// round 5
// speedup vs baseline: 1.1026x; 1.1026x over previous
#include <cuda_runtime.h>
#include <cuda_bf16.h>

// Problem: N = 50000 nodes, F = 2048 features, OUT = 256 outputs
//   v[i]   = sum_n adj[n] * fm[n, i]           (column-weighted sum, 409.6 MB read)
//   out[j] = sum_i (A[i] * v[i]) * B[i, j]     (tiny GEMV, ~2 MB)
// HBM-bound. Design: persistent work-stealing colsum (no pre-zero kernel),
// partial-sum GEMV, tiny finalize that also restores device state so the
// launch sequence is replay-invariant under CUDA graph timing.

#define F_DIM 2048
#define OUT_DIM 256

#define P1_THREADS 512            // thread t owns columns [4t, 4t+4) as float4
#define P1_BLOCKS 296             // 2 CTAs/SM * 148 SMs (occ 2 -> 64 regs/thread)
#define ROW_TILE 64               // rows per stolen work item (782 tiles total)

#define P2_BLOCKS 128
#define P2_ROWS (F_DIM / P2_BLOCKS)   // 16 i-rows per gemv block

// Device state. Zero at module load; finalize_kernel restores zeros at the end
// of every launch, so every kernel_launch call sees identical initial state.
__device__ float g_v[F_DIM];
__device__ float g_out_part[P2_BLOCKS * OUT_DIM];
__device__ int   g_ctr;

// ---------------------------------------------------------------------------
// Phase 1: v[i] += sum over stolen row-tiles of adj[n] * fm[n, i].
// Persistent CTAs steal 64-row tiles via a global counter to kill the
// per-SM finish-time spread. Unroll-by-8 float4 loads for MLP ~= 8.
// ---------------------------------------------------------------------------
__global__ __launch_bounds__(P1_THREADS, 2)
void colsum_kernel(const float* __restrict__ adj,
                   const float* __restrict__ fm,
                   int n_rows) {
    const int t = threadIdx.x;                       // 0..511
    const int n_tiles = (n_rows + ROW_TILE - 1) / ROW_TILE;
    const float4* __restrict__ fm4 = (const float4*)fm;

    float ax = 0.f, ay = 0.f, az = 0.f, aw = 0.f;

    __shared__ int s_tile;
    for (;;) {
        __syncthreads();
        if (t == 0) s_tile = atomicAdd(&g_ctr, 1);
        __syncthreads();
        const int tile = s_tile;
        if (tile >= n_tiles) break;

        const int r0 = tile * ROW_TILE;
        int rlen = n_rows - r0;
        if (rlen > ROW_TILE) rlen = ROW_TILE;

        int k = 0;
        for (; k + 8 <= rlen; k += 8) {
            const size_t base = (size_t)(r0 + k) * (F_DIM / 4) + t;
            // 8 independent 16B loads in flight before consumption.
            float4 x0 = __ldg(fm4 + base + 0 * (F_DIM / 4));
            float4 x1 = __ldg(fm4 + base + 1 * (F_DIM / 4));
            float4 x2 = __ldg(fm4 + base + 2 * (F_DIM / 4));
            float4 x3 = __ldg(fm4 + base + 3 * (F_DIM / 4));
            float4 x4 = __ldg(fm4 + base + 4 * (F_DIM / 4));
            float4 x5 = __ldg(fm4 + base + 5 * (F_DIM / 4));
            float4 x6 = __ldg(fm4 + base + 6 * (F_DIM / 4));
            float4 x7 = __ldg(fm4 + base + 7 * (F_DIM / 4));
            // adj values are warp-uniform broadcasts, L1/L2-hot (200 KB total).
            float a0 = __ldg(adj + r0 + k + 0);
            float a1 = __ldg(adj + r0 + k + 1);
            float a2 = __ldg(adj + r0 + k + 2);
            float a3 = __ldg(adj + r0 + k + 3);
            float a4 = __ldg(adj + r0 + k + 4);
            float a5 = __ldg(adj + r0 + k + 5);
            float a6 = __ldg(adj + r0 + k + 6);
            float a7 = __ldg(adj + r0 + k + 7);
            ax = fmaf(a0, x0.x, ax); ay = fmaf(a0, x0.y, ay);
            az = fmaf(a0, x0.z, az); aw = fmaf(a0, x0.w, aw);
            ax = fmaf(a1, x1.x, ax); ay = fmaf(a1, x1.y, ay);
            az = fmaf(a1, x1.z, az); aw = fmaf(a1, x1.w, aw);
            ax = fmaf(a2, x2.x, ax); ay = fmaf(a2, x2.y, ay);
            az = fmaf(a2, x2.z, az); aw = fmaf(a2, x2.w, aw);
            ax = fmaf(a3, x3.x, ax); ay = fmaf(a3, x3.y, ay);
            az = fmaf(a3, x3.z, az); aw = fmaf(a3, x3.w, aw);
            ax = fmaf(a4, x4.x, ax); ay = fmaf(a4, x4.y, ay);
            az = fmaf(a4, x4.z, az); aw = fmaf(a4, x4.w, aw);
            ax = fmaf(a5, x5.x, ax); ay = fmaf(a5, x5.y, ay);
            az = fmaf(a5, x5.z, az); aw = fmaf(a5, x5.w, aw);
            ax = fmaf(a6, x6.x, ax); ay = fmaf(a6, x6.y, ay);
            az = fmaf(a6, x6.z, az); aw = fmaf(a6, x6.w, aw);
            ax = fmaf(a7, x7.x, ax); ay = fmaf(a7, x7.y, ay);
            az = fmaf(a7, x7.z, az); aw = fmaf(a7, x7.w, aw);
        }
        for (; k < rlen; ++k) {
            float a = __ldg(adj + r0 + k);
            float4 x = __ldg(fm4 + (size_t)(r0 + k) * (F_DIM / 4) + t);
            ax = fmaf(a, x.x, ax); ay = fmaf(a, x.y, ay);
            az = fmaf(a, x.z, az); aw = fmaf(a, x.w, aw);
        }
    }

    // 296 collisions per address across 2048 addresses -> microseconds.
    atomicAdd(&g_v[4 * t + 0], ax);
    atomicAdd(&g_v[4 * t + 1], ay);
    atomicAdd(&g_v[4 * t + 2], az);
    atomicAdd(&g_v[4 * t + 3], aw);
}

// ---------------------------------------------------------------------------
// Phase 2: per-block partial GEMV. Block b covers i in [16b, 16b+16);
// thread j = output column. Plain stores to g_out_part (no atomics).
// ---------------------------------------------------------------------------
__global__ __launch_bounds__(OUT_DIM)
void gemv_kernel(const float* __restrict__ A,
                 const float* __restrict__ B) {
    __shared__ float av[P2_ROWS];
    const int j = threadIdx.x;                       // 0..255
    const int i0 = blockIdx.x * P2_ROWS;

    if (j < P2_ROWS) {
        int i = i0 + j;
        av[j] = A[i] * g_v[i];
    }
    __syncthreads();

    float s0 = 0.f, s1 = 0.f, s2 = 0.f, s3 = 0.f;
#pragma unroll
    for (int k = 0; k < P2_ROWS; k += 4) {
        size_t base = (size_t)(i0 + k) * OUT_DIM + j;
        s0 = fmaf(av[k + 0], __ldg(B + base + 0 * OUT_DIM), s0);
        s1 = fmaf(av[k + 1], __ldg(B + base + 1 * OUT_DIM), s1);
        s2 = fmaf(av[k + 2], __ldg(B + base + 2 * OUT_DIM), s2);
        s3 = fmaf(av[k + 3], __ldg(B + base + 3 * OUT_DIM), s3);
    }
    g_out_part[blockIdx.x * OUT_DIM + j] = (s0 + s1) + (s2 + s3);
}

// ---------------------------------------------------------------------------
// Phase 3: finalize. Sum the 128 partials per output column (plain store to
// d_out -- no pre-zero needed), then restore g_v/g_ctr to zero so the next
// graph replay sees the same initial device state.
// ---------------------------------------------------------------------------
__global__ __launch_bounds__(OUT_DIM)
void finalize_kernel(float* __restrict__ out) {
    const int j = threadIdx.x;                       // 0..255
    float s = 0.f;
#pragma unroll 8
    for (int b = 0; b < P2_BLOCKS; ++b)
        s += g_out_part[b * OUT_DIM + j];
    out[j] = s;

    // Restore invariants for the next launch.
#pragma unroll
    for (int k = 0; k < F_DIM / OUT_DIM; ++k)        // 8 each
        g_v[k * OUT_DIM + j] = 0.0f;
    if (j == 0) g_ctr = 0;
}

// ---------------------------------------------------------------------------
// Launch. Inputs (metadata order): node_adjacency [1,50000], feature_map
// [50000,2048], A [2048,1], B [2048,256], fe_mask_rate (scalar == 0, ignored).
// Output: float32 [1,256].
// ---------------------------------------------------------------------------
extern "C" void kernel_launch(void* const* d_in, const int* in_sizes, int n_in,
                              void* d_out, int out_size) {
    const float* adj = (const float*)d_in[0];
    const float* fm  = (const float*)d_in[1];
    const float* A   = (const float*)d_in[2];
    const float* B   = (const float*)d_in[3];
    float* out = (float*)d_out;

    const int n_rows = in_sizes[0];                  // 50000

    colsum_kernel<<<P1_BLOCKS, P1_THREADS>>>(adj, fm, n_rows);
    gemv_kernel<<<P2_BLOCKS, OUT_DIM>>>(A, B);
    finalize_kernel<<<1, OUT_DIM>>>(out);
}

// round 6
// speedup vs baseline: 1.1945x; 1.0834x over previous
#include <cuda_runtime.h>
#include <cuda_bf16.h>

// Problem: N = 50000 nodes, F = 2048 features, OUT = 256 outputs
//   v[i]   = sum_n adj[n] * fm[n, i]           (column-weighted sum, 409.6 MB read)
//   out[j] = sum_i (A[i] * v[i]) * B[i, j]     (tiny GEMV, ~2 MB)
// HBM-bound. Round 5 profile: colsum 69.8us @ 72.4% DRAM, regs=56;
// loss dominated by 2.64-tiles/CTA work-steal quantization (13%).
// Round 6: grid-stride static interleave (0.6% imbalance, no barriers/atomics
// in hot loop) + 2-launch pipeline (gemv accumulates into out directly and
// self-restores g_v for graph-replay invariance).

#define F_DIM 2048
#define OUT_DIM 256

#define P1_THREADS 512            // thread t owns columns [4t, 4t+4) as float4
#define P1_BLOCKS 296             // 2 CTAs/SM * 148 SMs (occ 2 -> 64 regs/thread)

#define P2_BLOCKS 128
#define P2_ROWS (F_DIM / P2_BLOCKS)   // 16 i-rows per gemv block

// Zero at module load; gemv_kernel restores zeros after reading, so every
// graph replay sees identical initial state.
__device__ float g_v[F_DIM];

// Streaming 16B load (read-once data: evict-first, keep L2 clean).
__device__ __forceinline__ float4 ldcs4(const float4* p) {
    float4 v;
    asm volatile("ld.global.cs.v4.f32 {%0,%1,%2,%3}, [%4];"
                 : "=f"(v.x), "=f"(v.y), "=f"(v.z), "=f"(v.w) : "l"(p));
    return v;
}

// ---------------------------------------------------------------------------
// Phase 1: v[i] = sum_n adj[n] * fm[n, i].
// CTA b owns rows {b, b+296, b+592, ...}: perfect 0.6% load balance, no
// synchronization in the hot loop. Each row is an 8 KB fully-coalesced burst
// (512 threads x float4). Unroll-by-8 rows for MLP ~= 8 per thread.
// Block 0 also zeroes the output buffer for phase 2's atomic accumulation.
// ---------------------------------------------------------------------------
__global__ __launch_bounds__(P1_THREADS, 2)
void colsum_kernel(const float* __restrict__ adj,
                   const float* __restrict__ fm,
                   int n_rows, float* __restrict__ out) {
    const int t = threadIdx.x;                       // 0..511
    const int b = blockIdx.x;                        // 0..295

    if (b == 0 && t < OUT_DIM) out[t] = 0.0f;        // harness poisons d_out

    const float4* __restrict__ fm4 = (const float4*)fm;
    const size_t rstride = F_DIM / 4;                // float4s per row

    float ax = 0.f, ay = 0.f, az = 0.f, aw = 0.f;

    int r = b;
    for (; r + 7 * P1_BLOCKS < n_rows; r += 8 * P1_BLOCKS) {
        // 8 independent 16B loads in flight before consumption.
        float4 x0 = ldcs4(fm4 + (size_t)(r + 0 * P1_BLOCKS) * rstride + t);
        float4 x1 = ldcs4(fm4 + (size_t)(r + 1 * P1_BLOCKS) * rstride + t);
        float4 x2 = ldcs4(fm4 + (size_t)(r + 2 * P1_BLOCKS) * rstride + t);
        float4 x3 = ldcs4(fm4 + (size_t)(r + 3 * P1_BLOCKS) * rstride + t);
        float4 x4 = ldcs4(fm4 + (size_t)(r + 4 * P1_BLOCKS) * rstride + t);
        float4 x5 = ldcs4(fm4 + (size_t)(r + 5 * P1_BLOCKS) * rstride + t);
        float4 x6 = ldcs4(fm4 + (size_t)(r + 6 * P1_BLOCKS) * rstride + t);
        float4 x7 = ldcs4(fm4 + (size_t)(r + 7 * P1_BLOCKS) * rstride + t);
        // adj values: warp-uniform broadcasts, 200 KB total, L2-hot.
        float a0 = __ldg(adj + r + 0 * P1_BLOCKS);
        float a1 = __ldg(adj + r + 1 * P1_BLOCKS);
        float a2 = __ldg(adj + r + 2 * P1_BLOCKS);
        float a3 = __ldg(adj + r + 3 * P1_BLOCKS);
        float a4 = __ldg(adj + r + 4 * P1_BLOCKS);
        float a5 = __ldg(adj + r + 5 * P1_BLOCKS);
        float a6 = __ldg(adj + r + 6 * P1_BLOCKS);
        float a7 = __ldg(adj + r + 7 * P1_BLOCKS);
        ax = fmaf(a0, x0.x, ax); ay = fmaf(a0, x0.y, ay);
        az = fmaf(a0, x0.z, az); aw = fmaf(a0, x0.w, aw);
        ax = fmaf(a1, x1.x, ax); ay = fmaf(a1, x1.y, ay);
        az = fmaf(a1, x1.z, az); aw = fmaf(a1, x1.w, aw);
        ax = fmaf(a2, x2.x, ax); ay = fmaf(a2, x2.y, ay);
        az = fmaf(a2, x2.z, az); aw = fmaf(a2, x2.w, aw);
        ax = fmaf(a3, x3.x, ax); ay = fmaf(a3, x3.y, ay);
        az = fmaf(a3, x3.z, az); aw = fmaf(a3, x3.w, aw);
        ax = fmaf(a4, x4.x, ax); ay = fmaf(a4, x4.y, ay);
        az = fmaf(a4, x4.z, az); aw = fmaf(a4, x4.w, aw);
        ax = fmaf(a5, x5.x, ax); ay = fmaf(a5, x5.y, ay);
        az = fmaf(a5, x5.z, az); aw = fmaf(a5, x5.w, aw);
        ax = fmaf(a6, x6.x, ax); ay = fmaf(a6, x6.y, ay);
        az = fmaf(a6, x6.z, az); aw = fmaf(a6, x6.w, aw);
        ax = fmaf(a7, x7.x, ax); ay = fmaf(a7, x7.y, ay);
        az = fmaf(a7, x7.z, az); aw = fmaf(a7, x7.w, aw);
    }
    for (; r < n_rows; r += P1_BLOCKS) {
        float a = __ldg(adj + r);
        float4 x = ldcs4(fm4 + (size_t)r * rstride + t);
        ax = fmaf(a, x.x, ax); ay = fmaf(a, x.y, ay);
        az = fmaf(a, x.z, az); aw = fmaf(a, x.w, aw);
    }

    // 296 collisions per address across 2048 addresses -> microseconds.
    atomicAdd(&g_v[4 * t + 0], ax);
    atomicAdd(&g_v[4 * t + 1], ay);
    atomicAdd(&g_v[4 * t + 2], az);
    atomicAdd(&g_v[4 * t + 3], aw);
}

// ---------------------------------------------------------------------------
// Phase 2: out[j] += sum_{i in block} A[i]*v[i]*B[i, j], accumulated with
// atomics (128 adds/address). Each block then restores its 16 g_v entries to
// zero so the next graph replay sees pristine device state.
// ---------------------------------------------------------------------------
__global__ __launch_bounds__(OUT_DIM)
void gemv_kernel(const float* __restrict__ A,
                 const float* __restrict__ B,
                 float* __restrict__ out) {
    __shared__ float av[P2_ROWS];
    const int j = threadIdx.x;                       // 0..255
    const int i0 = blockIdx.x * P2_ROWS;

    if (j < P2_ROWS) {
        int i = i0 + j;
        av[j] = A[i] * g_v[i];
        g_v[i] = 0.0f;                               // restore for next replay
    }
    __syncthreads();

    float s0 = 0.f, s1 = 0.f, s2 = 0.f, s3 = 0.f;
#pragma unroll
    for (int k = 0; k < P2_ROWS; k += 4) {
        size_t base = (size_t)(i0 + k) * OUT_DIM + j;
        s0 = fmaf(av[k + 0], __ldg(B + base + 0 * OUT_DIM), s0);
        s1 = fmaf(av[k + 1], __ldg(B + base + 1 * OUT_DIM), s1);
        s2 = fmaf(av[k + 2], __ldg(B + base + 2 * OUT_DIM), s2);
        s3 = fmaf(av[k + 3], __ldg(B + base + 3 * OUT_DIM), s3);
    }
    atomicAdd(&out[j], (s0 + s1) + (s2 + s3));
}

// ---------------------------------------------------------------------------
// Launch. Inputs (metadata order): node_adjacency [1,50000], feature_map
// [50000,2048], A [2048,1], B [2048,256], fe_mask_rate (scalar == 0, ignored).
// Output: float32 [1,256].
// ---------------------------------------------------------------------------
extern "C" void kernel_launch(void* const* d_in, const int* in_sizes, int n_in,
                              void* d_out, int out_size) {
    const float* adj = (const float*)d_in[0];
    const float* fm  = (const float*)d_in[1];
    const float* A   = (const float*)d_in[2];
    const float* B   = (const float*)d_in[3];
    float* out = (float*)d_out;

    const int n_rows = in_sizes[0];                  // 50000

    colsum_kernel<<<P1_BLOCKS, P1_THREADS>>>(adj, fm, n_rows, out);
    gemv_kernel<<<P2_BLOCKS, OUT_DIM>>>(A, B, out);
}